// round 14
// baseline (speedup 1.0000x reference)
#include <cuda_runtime.h>
#include <cuda_bf16.h>
#include <math.h>
#include <stdint.h>

#define VOCAB 50000
#define DIM   300
#define BATCH 1024
#define CTX   10
#define KP    320            // storage K (rows are 320 bf16); cols 304..319 zero
#define NVT   391            // vocab tiles of 128
#define NV    (NVT * 128)
#define NBT   8              // batch tiles of 128
#define NCH   5              // k-chunks of 64 cols (last chunk: only 3 k-steps)
#define ROWB  640            // bf16 row stride bytes
#define VSTR  50048          // logit scratch row stride
#define NCONV (NV * 40 / 320)  // 6256 convert blocks @320 thr
#define SUBSPLIT 2           // blocks per batch row in fused lse+sub
#define HGRP  (VOCAB / 8 / SUBSPLIT)   // 3125 8-elem groups per half row

__device__ uint4 g_Wcb[(size_t)NV * 40];            // [NV][320] bf16 (bias at col 300)
__device__ uint4 g_poolb[BATCH * 40];               // [1024][320] bf16 (col 300 = 1)
__device__ __nv_bfloat16 g_logit[(size_t)BATCH * VSTR];
__device__ float g_psum[BATCH * NVT];               // [b][vt]

__device__ __forceinline__ uint32_t smem_u32(const void* p) {
    uint32_t a;
    asm("{ .reg .u64 t; cvta.to.shared.u64 t, %1; cvt.u32.u64 %0, t; }" : "=r"(a) : "l"(p));
    return a;
}
__device__ __forceinline__ void cp_async16(uint32_t saddr, const void* g) {
    asm volatile("cp.async.cg.shared.global [%0], [%1], 16;\n" :: "r"(saddr), "l"(g));
}
#define CP_COMMIT() asm volatile("cp.async.commit_group;\n")
#define CP_WAIT(n)  asm volatile("cp.async.wait_group %0;\n" :: "n"(n) : "memory")

#define LDSM_X4(r0, r1, r2, r3, addr) \
    asm volatile("ldmatrix.sync.aligned.m8n8.x4.shared.b16 {%0,%1,%2,%3}, [%4];" \
        : "=r"(r0), "=r"(r1), "=r"(r2), "=r"(r3) : "r"(addr))

#define MMA16816(d, a0, a1, a2, a3, b0, b1) \
    asm volatile("mma.sync.aligned.m16n8k16.row.col.f32.bf16.bf16.f32 " \
        "{%0,%1,%2,%3}, {%4,%5,%6,%7}, {%8,%9}, {%0,%1,%2,%3};\n" \
        : "+f"((d)[0]), "+f"((d)[1]), "+f"((d)[2]), "+f"((d)[3]) \
        : "r"(a0), "r"(a1), "r"(a2), "r"(a3), "r"(b0), "r"(b1))

// ---------------------------------------------------------------------------
// Kernel A: fused prep. Blocks [0, 1024): pooling. Blocks [1024, 1024+NCONV):
// W_cls fp32 -> bf16 [NV][320] with bias folded at col 300.
// ---------------------------------------------------------------------------
__global__ void __launch_bounds__(320)
prep_kernel(const int* __restrict__ ctx, const float* __restrict__ Wp,
            const int* __restrict__ pad_idx,
            const float* __restrict__ Wc, const float* __restrict__ bc) {
    if (blockIdx.x < BATCH) {
        int b = blockIdx.x;
        __shared__ int ids[CTX];
        __shared__ int pad;
        __shared__ __align__(16) __nv_bfloat16 sv[KP];
        if (threadIdx.x < CTX) ids[threadIdx.x] = ctx[b * CTX + threadIdx.x];
        if (threadIdx.x == 0)  pad = *pad_idx;
        __syncthreads();
        int d = threadIdx.x;
        float s = 0.f;
        if (d < DIM) {
            #pragma unroll
            for (int c = 0; c < CTX; ++c) {
                int id = ids[c];
                if (id != pad) s += Wp[(size_t)d * VOCAB + id];
            }
            s *= (1.0f / CTX);
        } else if (d == DIM) {
            s = 1.0f;                              // bias multiplier at col 300
        }
        sv[d] = __float2bfloat16(s);
        __syncthreads();
        if (d < 40) g_poolb[b * 40 + d] = ((const uint4*)sv)[d];
    } else {
        int idx = (blockIdx.x - BATCH) * 320 + threadIdx.x;
        if (idx >= NV * 40) return;
        int v = idx / 40, j = idx % 40, k8 = j * 8;
        __nv_bfloat16 h[8];
        uint32_t* hu = (uint32_t*)h;
        hu[0] = hu[1] = hu[2] = hu[3] = 0u;
        if (v < VOCAB) {
            if (k8 + 8 <= DIM) {
                const float4 f0 = *(const float4*)(Wc + (size_t)v * DIM + k8);
                const float4 f1 = *(const float4*)(Wc + (size_t)v * DIM + k8 + 4);
                h[0] = __float2bfloat16(f0.x); h[1] = __float2bfloat16(f0.y);
                h[2] = __float2bfloat16(f0.z); h[3] = __float2bfloat16(f0.w);
                h[4] = __float2bfloat16(f1.x); h[5] = __float2bfloat16(f1.y);
                h[6] = __float2bfloat16(f1.z); h[7] = __float2bfloat16(f1.w);
            } else {
                #pragma unroll
                for (int jj = 0; jj < 8; ++jj) {
                    int k = k8 + jj;
                    float f = 0.f;
                    if (k < DIM) f = Wc[(size_t)v * DIM + k];
                    else if (k == DIM) f = bc[v];   // bias at col 300
                    h[jj] = __float2bfloat16(f);
                }
            }
        }
        g_Wcb[(size_t)v * 40 + j] = *(const uint4*)h;
    }
}

// ---------------------------------------------------------------------------
// Kernel C: R7 HMMA GEMM. M=batch(128), N=vocab(128), K=304 (19 k16 steps).
// 8 warps (2m x 4n), warp 64x32, 3-stage cp.async pipeline.
// ---------------------------------------------------------------------------
#define STG_BYTES 32768u
#define S_TR      0u
#define TRPITCH   272
#define S_LS      36864u
#define SMEM_REQ  (3 * 32768)

__device__ __forceinline__ void issue_chunk(uint32_t smbase, int s, int c,
                                            int bbase, int vbase, int tid) {
    const char* gP = (const char*)g_poolb + (size_t)bbase * ROWB + c * 128;
    const char* gW = (const char*)g_Wcb  + (size_t)vbase * ROWB + c * 128;
    uint32_t sP = smbase + (uint32_t)s * STG_BYTES;
    uint32_t sW = sP + 16384u;
    #pragma unroll
    for (int it = 0; it < 4; ++it) {
        int idx = tid + it * 256;
        int row = idx >> 3, ju = idx & 7;
        uint32_t soff = (uint32_t)((row * 8 + (ju ^ (row & 7))) * 16);
        cp_async16(sP + soff, gP + (size_t)row * ROWB + ju * 16);
        cp_async16(sW + soff, gW + (size_t)row * ROWB + ju * 16);
    }
    CP_COMMIT();
}

__device__ __forceinline__ void do_kstep(uint32_t sP, uint32_t sW, int ks,
                                         int wm, int wn, int r16, int uhi,
                                         float acc[4][4][4]) {
    const int uu = 2 * ks + uhi;
    uint32_t a[4][4], b[4][2];
    #pragma unroll
    for (int mi = 0; mi < 4; ++mi) {
        int row = wm * 64 + mi * 16 + r16;
        uint32_t ad = sP + (uint32_t)((row * 8 + (uu ^ (row & 7))) * 16);
        LDSM_X4(a[mi][0], a[mi][1], a[mi][2], a[mi][3], ad);
    }
    #pragma unroll
    for (int nj = 0; nj < 2; ++nj) {
        int row = wn * 32 + nj * 16 + r16;
        uint32_t ad = sW + (uint32_t)((row * 8 + (uu ^ (row & 7))) * 16);
        uint32_t r0, r1, r2, r3;
        LDSM_X4(r0, r1, r2, r3, ad);
        b[2*nj][0] = r0; b[2*nj+1][0] = r1;
        b[2*nj][1] = r2; b[2*nj+1][1] = r3;
    }
    #pragma unroll
    for (int mi = 0; mi < 4; ++mi)
        #pragma unroll
        for (int ni = 0; ni < 4; ++ni)
            MMA16816(acc[mi][ni], a[mi][0], a[mi][1], a[mi][2], a[mi][3],
                     b[ni][0], b[ni][1]);
}

__global__ void __launch_bounds__(256, 2)
gemm_kernel() {
    extern __shared__ char smc[];
    const uint32_t smbase = smem_u32(smc);

    const int tid = threadIdx.x, wid = tid >> 5, lane = tid & 31;
    const int wm = wid >> 2, wn = wid & 3;
    const int g = lane >> 2, t = lane & 3;
    const int vt = blockIdx.y, bt = blockIdx.x;
    const int vbase = vt * 128, bbase = bt * 128;

    float acc[4][4][4];
    #pragma unroll
    for (int mi = 0; mi < 4; ++mi)
        #pragma unroll
        for (int ni = 0; ni < 4; ++ni)
            { acc[mi][ni][0] = acc[mi][ni][1] = acc[mi][ni][2] = acc[mi][ni][3] = 0.f; }

    issue_chunk(smbase, 0, 0, bbase, vbase, tid);
    issue_chunk(smbase, 1, 1, bbase, vbase, tid);

    const int r16 = lane & 15, uhi = lane >> 4;

    for (int c = 0; c < NCH; ++c) {
        if (c < NCH - 1) CP_WAIT(1); else CP_WAIT(0);
        __syncthreads();
        if (c + 2 < NCH) issue_chunk(smbase, (c + 2) % 3, c + 2, bbase, vbase, tid);

        uint32_t sP = smbase + (uint32_t)(c % 3) * STG_BYTES;
        uint32_t sW = sP + 16384u;

        if (c < NCH - 1) {
            #pragma unroll
            for (int ks = 0; ks < 4; ++ks)
                do_kstep(sP, sW, ks, wm, wn, r16, uhi, acc);
        } else {
            #pragma unroll
            for (int ks = 0; ks < 3; ++ks)       // cols 304..319 are zero
                do_kstep(sP, sW, ks, wm, wn, r16, uhi, acc);
        }
    }
    __syncthreads();

    // ---- stage tile into smem (transpose) ----
    #pragma unroll
    for (int mi = 0; mi < 4; ++mi) {
        int rg = wm * 64 + mi * 16 + g;
        #pragma unroll
        for (int ni = 0; ni < 4; ++ni) {
            int c0 = wn * 32 + ni * 8 + 2 * t;
            __nv_bfloat162 p0, p1;
            p0.x = __float2bfloat16(acc[mi][ni][0]);
            p0.y = __float2bfloat16(acc[mi][ni][1]);
            p1.x = __float2bfloat16(acc[mi][ni][2]);
            p1.y = __float2bfloat16(acc[mi][ni][3]);
            *(__nv_bfloat162*)(smc + S_TR + rg * TRPITCH + c0 * 2)       = p0;
            *(__nv_bfloat162*)(smc + S_TR + (rg + 8) * TRPITCH + c0 * 2) = p1;
        }
    }

    // ---- sum-exp partials (no max shift; logits are O(1)) ----
    bool ok0[4], ok1[4];
    #pragma unroll
    for (int ni = 0; ni < 4; ++ni) {
        int c0 = vbase + wn * 32 + ni * 8 + 2 * t;
        ok0[ni] = c0 < VOCAB;
        ok1[ni] = (c0 + 1) < VOCAB;
    }
    float rs[4][2];
    #pragma unroll
    for (int mi = 0; mi < 4; ++mi) {
        rs[mi][0] = rs[mi][1] = 0.f;
        #pragma unroll
        for (int ni = 0; ni < 4; ++ni) {
            if (ok0[ni]) { rs[mi][0] += __expf(acc[mi][ni][0]);
                           rs[mi][1] += __expf(acc[mi][ni][2]); }
            if (ok1[ni]) { rs[mi][0] += __expf(acc[mi][ni][1]);
                           rs[mi][1] += __expf(acc[mi][ni][3]); }
        }
    }
    float* ls = (float*)(smc + S_LS);
    #pragma unroll
    for (int mi = 0; mi < 4; ++mi)
        #pragma unroll
        for (int p = 0; p < 2; ++p) {
            rs[mi][p] += __shfl_xor_sync(0xffffffffu, rs[mi][p], 1);
            rs[mi][p] += __shfl_xor_sync(0xffffffffu, rs[mi][p], 2);
            if (t == 0)
                ls[wn * 128 + wm * 64 + mi * 16 + g + p * 8] = rs[mi][p];
        }
    __syncthreads();

    // ---- coalesced 16B logit stores ----
    {
        int r = tid >> 1, half = tid & 1;
        const char* src = smc + S_TR + r * TRPITCH + half * 128;
        __nv_bfloat16* dst = g_logit + (size_t)(bbase + r) * VSTR + vbase + half * 64;
        #pragma unroll
        for (int k = 0; k < 8; ++k)
            *(uint4*)(dst + k * 8) = *(const uint4*)(src + k * 16);
    }

    if (tid < 128) {
        float s = ls[tid] + ls[128 + tid] + ls[256 + tid] + ls[384 + tid];
        g_psum[(size_t)(bbase + tid) * NVT + vt] = s;
    }
}

// ---------------------------------------------------------------------------
// Kernel D: fused lse + sub. Two blocks per batch row; each block reduces the
// row's psum partials (1.6KB) to lse, then streams its half-row subtraction.
// ---------------------------------------------------------------------------
__global__ void __launch_bounds__(256)
subfused_kernel(float* __restrict__ out) {
    const int b    = blockIdx.x >> 1;
    const int half = blockIdx.x & 1;
    const int t    = threadIdx.x;

    // lse for row b (redundant across the 2 blocks; reads are L2-shared)
    const float* ps = g_psum + (size_t)b * NVT;
    float s = 0.f;
    for (int v = t; v < NVT; v += 256) s += ps[v];
    #pragma unroll
    for (int off = 16; off > 0; off >>= 1)
        s += __shfl_xor_sync(0xffffffffu, s, off);
    __shared__ float ssum[8];
    if ((t & 31) == 0) ssum[t >> 5] = s;
    __syncthreads();
    __shared__ float lse_s;
    if (t == 0) {
        float tot = ssum[0] + ssum[1] + ssum[2] + ssum[3]
                  + ssum[4] + ssum[5] + ssum[6] + ssum[7];
        lse_s = logf(tot);
    }
    __syncthreads();
    const float l = lse_s;

    const __nv_bfloat16* src = g_logit + (size_t)b * VSTR;
    float* dst = out + (size_t)b * VOCAB;
    for (int j8 = half * HGRP + t; j8 < (half + 1) * HGRP; j8 += 256) {
        const uint4 pkt = *(const uint4*)(src + j8 * 8);
        const __nv_bfloat16* h = (const __nv_bfloat16*)&pkt;
        float4 o0, o1;
        o0.x = __bfloat162float(h[0]) - l; o0.y = __bfloat162float(h[1]) - l;
        o0.z = __bfloat162float(h[2]) - l; o0.w = __bfloat162float(h[3]) - l;
        o1.x = __bfloat162float(h[4]) - l; o1.y = __bfloat162float(h[5]) - l;
        o1.z = __bfloat162float(h[6]) - l; o1.w = __bfloat162float(h[7]) - l;
        float4* op = (float4*)(dst + j8 * 8);
        op[0] = o0; op[1] = o1;
    }
}

extern "C" void kernel_launch(void* const* d_in, const int* in_sizes, int n_in,
                              void* d_out, int out_size) {
    const int*   ctx = (const int*)d_in[0];
    const float* Wp  = (const float*)d_in[1];
    const float* Wc  = (const float*)d_in[2];
    const float* bc  = (const float*)d_in[3];
    const int*   pad = (const int*)d_in[4];
    float*       out = (float*)d_out;

    cudaFuncSetAttribute(gemm_kernel, cudaFuncAttributeMaxDynamicSharedMemorySize, SMEM_REQ);

    prep_kernel<<<BATCH + NCONV, 320>>>(ctx, Wp, pad, Wc, bc);   // idx 0
    gemm_kernel<<<dim3(NBT, NVT), 256, SMEM_REQ>>>();            // idx 1
    subfused_kernel<<<BATCH * SUBSPLIT, 256>>>(out);             // idx 2
}

// round 15
// speedup vs baseline: 1.0436x; 1.0436x over previous
#include <cuda_runtime.h>
#include <cuda_bf16.h>
#include <math.h>
#include <stdint.h>

#define VOCAB 50000
#define DIM   300
#define BATCH 1024
#define CTX   10
#define KP    320            // storage K (rows are 320 bf16); cols 304..319 zero
#define NVT   391            // vocab tiles of 128
#define NV    (NVT * 128)
#define NBT   8              // batch tiles of 128
#define NCH   5              // k-chunks of 64 cols (last chunk: only 3 k-steps)
#define ROWB  640            // bf16 row stride bytes
#define VSTR  50048          // logit scratch row stride
#define NCONV (NV * 40 / 320)  // 6256 convert blocks @320 thr

__device__ uint4 g_Wcb[(size_t)NV * 40];            // [NV][320] bf16 (bias at col 300)
__device__ uint4 g_poolb[BATCH * 40];               // [1024][320] bf16 (col 300 = 1)
__device__ __nv_bfloat16 g_logit[(size_t)BATCH * VSTR];
__device__ float g_psum[BATCH * NVT];               // [b][vt]
__device__ float g_lse[BATCH];

__device__ __forceinline__ uint32_t smem_u32(const void* p) {
    uint32_t a;
    asm("{ .reg .u64 t; cvta.to.shared.u64 t, %1; cvt.u32.u64 %0, t; }" : "=r"(a) : "l"(p));
    return a;
}
__device__ __forceinline__ void cp_async16(uint32_t saddr, const void* g) {
    asm volatile("cp.async.cg.shared.global [%0], [%1], 16;\n" :: "r"(saddr), "l"(g));
}
#define CP_COMMIT() asm volatile("cp.async.commit_group;\n")
#define CP_WAIT(n)  asm volatile("cp.async.wait_group %0;\n" :: "n"(n) : "memory")

#define LDSM_X4(r0, r1, r2, r3, addr) \
    asm volatile("ldmatrix.sync.aligned.m8n8.x4.shared.b16 {%0,%1,%2,%3}, [%4];" \
        : "=r"(r0), "=r"(r1), "=r"(r2), "=r"(r3) : "r"(addr))

#define MMA16816(d, a0, a1, a2, a3, b0, b1) \
    asm volatile("mma.sync.aligned.m16n8k16.row.col.f32.bf16.bf16.f32 " \
        "{%0,%1,%2,%3}, {%4,%5,%6,%7}, {%8,%9}, {%0,%1,%2,%3};\n" \
        : "+f"((d)[0]), "+f"((d)[1]), "+f"((d)[2]), "+f"((d)[3]) \
        : "r"(a0), "r"(a1), "r"(a2), "r"(a3), "r"(b0), "r"(b1))

// ---------------------------------------------------------------------------
// Kernel A: fused prep. Blocks [0, 1024): pooling. Blocks [1024, 1024+NCONV):
// W_cls fp32 -> bf16 [NV][320] with bias folded at col 300.
// ---------------------------------------------------------------------------
__global__ void __launch_bounds__(320)
prep_kernel(const int* __restrict__ ctx, const float* __restrict__ Wp,
            const int* __restrict__ pad_idx,
            const float* __restrict__ Wc, const float* __restrict__ bc) {
    if (blockIdx.x < BATCH) {
        int b = blockIdx.x;
        __shared__ int ids[CTX];
        __shared__ int pad;
        __shared__ __align__(16) __nv_bfloat16 sv[KP];
        if (threadIdx.x < CTX) ids[threadIdx.x] = ctx[b * CTX + threadIdx.x];
        if (threadIdx.x == 0)  pad = *pad_idx;
        __syncthreads();
        int d = threadIdx.x;
        float s = 0.f;
        if (d < DIM) {
            #pragma unroll
            for (int c = 0; c < CTX; ++c) {
                int id = ids[c];
                if (id != pad) s += __ldg(Wp + (size_t)d * VOCAB + id);
            }
            s *= (1.0f / CTX);
        } else if (d == DIM) {
            s = 1.0f;                              // bias multiplier at col 300
        }
        sv[d] = __float2bfloat16(s);
        __syncthreads();
        if (d < 40) g_poolb[b * 40 + d] = ((const uint4*)sv)[d];
    } else {
        int idx = (blockIdx.x - BATCH) * 320 + threadIdx.x;
        if (idx >= NV * 40) return;
        int v = idx / 40, j = idx % 40, k8 = j * 8;
        __nv_bfloat16 h[8];
        uint32_t* hu = (uint32_t*)h;
        hu[0] = hu[1] = hu[2] = hu[3] = 0u;
        if (v < VOCAB) {
            if (k8 + 8 <= DIM) {
                const float4 f0 = *(const float4*)(Wc + (size_t)v * DIM + k8);
                const float4 f1 = *(const float4*)(Wc + (size_t)v * DIM + k8 + 4);
                h[0] = __float2bfloat16(f0.x); h[1] = __float2bfloat16(f0.y);
                h[2] = __float2bfloat16(f0.z); h[3] = __float2bfloat16(f0.w);
                h[4] = __float2bfloat16(f1.x); h[5] = __float2bfloat16(f1.y);
                h[6] = __float2bfloat16(f1.z); h[7] = __float2bfloat16(f1.w);
            } else {
                #pragma unroll
                for (int jj = 0; jj < 8; ++jj) {
                    int k = k8 + jj;
                    float f = 0.f;
                    if (k < DIM) f = Wc[(size_t)v * DIM + k];
                    else if (k == DIM) f = bc[v];   // bias at col 300
                    h[jj] = __float2bfloat16(f);
                }
            }
        }
        g_Wcb[(size_t)v * 40 + j] = *(const uint4*)h;
    }
}

// ---------------------------------------------------------------------------
// Kernel C: R7 HMMA GEMM. M=batch(128), N=vocab(128), K=304 (19 k16 steps).
// 8 warps (2m x 4n), warp 64x32, 3-stage cp.async pipeline.
// ---------------------------------------------------------------------------
#define STG_BYTES 32768u
#define S_TR      0u
#define TRPITCH   272
#define S_LS      36864u
#define SMEM_REQ  (3 * 32768)

__device__ __forceinline__ void issue_chunk(uint32_t smbase, int s, int c,
                                            int bbase, int vbase, int tid) {
    const char* gP = (const char*)g_poolb + (size_t)bbase * ROWB + c * 128;
    const char* gW = (const char*)g_Wcb  + (size_t)vbase * ROWB + c * 128;
    uint32_t sP = smbase + (uint32_t)s * STG_BYTES;
    uint32_t sW = sP + 16384u;
    #pragma unroll
    for (int it = 0; it < 4; ++it) {
        int idx = tid + it * 256;
        int row = idx >> 3, ju = idx & 7;
        uint32_t soff = (uint32_t)((row * 8 + (ju ^ (row & 7))) * 16);
        cp_async16(sP + soff, gP + (size_t)row * ROWB + ju * 16);
        cp_async16(sW + soff, gW + (size_t)row * ROWB + ju * 16);
    }
    CP_COMMIT();
}

__device__ __forceinline__ void do_kstep(uint32_t sP, uint32_t sW, int ks,
                                         int wm, int wn, int r16, int uhi,
                                         float acc[4][4][4]) {
    const int uu = 2 * ks + uhi;
    uint32_t a[4][4], b[4][2];
    #pragma unroll
    for (int mi = 0; mi < 4; ++mi) {
        int row = wm * 64 + mi * 16 + r16;
        uint32_t ad = sP + (uint32_t)((row * 8 + (uu ^ (row & 7))) * 16);
        LDSM_X4(a[mi][0], a[mi][1], a[mi][2], a[mi][3], ad);
    }
    #pragma unroll
    for (int nj = 0; nj < 2; ++nj) {
        int row = wn * 32 + nj * 16 + r16;
        uint32_t ad = sW + (uint32_t)((row * 8 + (uu ^ (row & 7))) * 16);
        uint32_t r0, r1, r2, r3;
        LDSM_X4(r0, r1, r2, r3, ad);
        b[2*nj][0] = r0; b[2*nj+1][0] = r1;
        b[2*nj][1] = r2; b[2*nj+1][1] = r3;
    }
    #pragma unroll
    for (int mi = 0; mi < 4; ++mi)
        #pragma unroll
        for (int ni = 0; ni < 4; ++ni)
            MMA16816(acc[mi][ni], a[mi][0], a[mi][1], a[mi][2], a[mi][3],
                     b[ni][0], b[ni][1]);
}

__global__ void __launch_bounds__(256, 2)
gemm_kernel() {
    extern __shared__ char smc[];
    const uint32_t smbase = smem_u32(smc);

    const int tid = threadIdx.x, wid = tid >> 5, lane = tid & 31;
    const int wm = wid >> 2, wn = wid & 3;
    const int g = lane >> 2, t = lane & 3;
    const int vt = blockIdx.y, bt = blockIdx.x;
    const int vbase = vt * 128, bbase = bt * 128;

    float acc[4][4][4];
    #pragma unroll
    for (int mi = 0; mi < 4; ++mi)
        #pragma unroll
        for (int ni = 0; ni < 4; ++ni)
            { acc[mi][ni][0] = acc[mi][ni][1] = acc[mi][ni][2] = acc[mi][ni][3] = 0.f; }

    issue_chunk(smbase, 0, 0, bbase, vbase, tid);
    issue_chunk(smbase, 1, 1, bbase, vbase, tid);

    const int r16 = lane & 15, uhi = lane >> 4;

    for (int c = 0; c < NCH; ++c) {
        if (c < NCH - 1) CP_WAIT(1); else CP_WAIT(0);
        __syncthreads();
        if (c + 2 < NCH) issue_chunk(smbase, (c + 2) % 3, c + 2, bbase, vbase, tid);

        uint32_t sP = smbase + (uint32_t)(c % 3) * STG_BYTES;
        uint32_t sW = sP + 16384u;

        if (c < NCH - 1) {
            #pragma unroll
            for (int ks = 0; ks < 4; ++ks)
                do_kstep(sP, sW, ks, wm, wn, r16, uhi, acc);
        } else {
            #pragma unroll
            for (int ks = 0; ks < 3; ++ks)       // cols 304..319 are zero
                do_kstep(sP, sW, ks, wm, wn, r16, uhi, acc);
        }
    }
    __syncthreads();

    // ---- stage tile into smem (transpose) ----
    #pragma unroll
    for (int mi = 0; mi < 4; ++mi) {
        int rg = wm * 64 + mi * 16 + g;
        #pragma unroll
        for (int ni = 0; ni < 4; ++ni) {
            int c0 = wn * 32 + ni * 8 + 2 * t;
            __nv_bfloat162 p0, p1;
            p0.x = __float2bfloat16(acc[mi][ni][0]);
            p0.y = __float2bfloat16(acc[mi][ni][1]);
            p1.x = __float2bfloat16(acc[mi][ni][2]);
            p1.y = __float2bfloat16(acc[mi][ni][3]);
            *(__nv_bfloat162*)(smc + S_TR + rg * TRPITCH + c0 * 2)       = p0;
            *(__nv_bfloat162*)(smc + S_TR + (rg + 8) * TRPITCH + c0 * 2) = p1;
        }
    }

    // ---- sum-exp partials (no max shift; logits are O(1)) ----
    bool ok0[4], ok1[4];
    #pragma unroll
    for (int ni = 0; ni < 4; ++ni) {
        int c0 = vbase + wn * 32 + ni * 8 + 2 * t;
        ok0[ni] = c0 < VOCAB;
        ok1[ni] = (c0 + 1) < VOCAB;
    }
    float rs[4][2];
    #pragma unroll
    for (int mi = 0; mi < 4; ++mi) {
        rs[mi][0] = rs[mi][1] = 0.f;
        #pragma unroll
        for (int ni = 0; ni < 4; ++ni) {
            if (ok0[ni]) { rs[mi][0] += __expf(acc[mi][ni][0]);
                           rs[mi][1] += __expf(acc[mi][ni][2]); }
            if (ok1[ni]) { rs[mi][0] += __expf(acc[mi][ni][1]);
                           rs[mi][1] += __expf(acc[mi][ni][3]); }
        }
    }
    float* ls = (float*)(smc + S_LS);
    #pragma unroll
    for (int mi = 0; mi < 4; ++mi)
        #pragma unroll
        for (int p = 0; p < 2; ++p) {
            rs[mi][p] += __shfl_xor_sync(0xffffffffu, rs[mi][p], 1);
            rs[mi][p] += __shfl_xor_sync(0xffffffffu, rs[mi][p], 2);
            if (t == 0)
                ls[wn * 128 + wm * 64 + mi * 16 + g + p * 8] = rs[mi][p];
        }
    __syncthreads();

    // ---- coalesced 16B logit stores ----
    {
        int r = tid >> 1, half = tid & 1;
        const char* src = smc + S_TR + r * TRPITCH + half * 128;
        __nv_bfloat16* dst = g_logit + (size_t)(bbase + r) * VSTR + vbase + half * 64;
        #pragma unroll
        for (int k = 0; k < 8; ++k)
            *(uint4*)(dst + k * 8) = *(const uint4*)(src + k * 16);
    }

    if (tid < 128) {
        float s = ls[tid] + ls[128 + tid] + ls[256 + tid] + ls[384 + tid];
        g_psum[(size_t)(bbase + tid) * NVT + vt] = s;
    }
}

// ---------------------------------------------------------------------------
// Kernel D: lse reduce — one block per batch row, plain sum (256 threads).
// ---------------------------------------------------------------------------
__global__ void lse_kernel() {
    int b = blockIdx.x;
    int t = threadIdx.x;
    const float* ps = g_psum + (size_t)b * NVT;
    float s = 0.f;
    for (int v = t; v < NVT; v += 256) s += ps[v];
    #pragma unroll
    for (int off = 16; off > 0; off >>= 1)
        s += __shfl_xor_sync(0xffffffffu, s, off);
    __shared__ float ss[8];
    if ((t & 31) == 0) ss[t >> 5] = s;
    __syncthreads();
    if (t == 0)
        g_lse[b] = logf(ss[0] + ss[1] + ss[2] + ss[3] +
                        ss[4] + ss[5] + ss[6] + ss[7]);
}

// ---------------------------------------------------------------------------
// Kernel E: out[b,v] = bf16_logit[b,v] - lse[b]
// ---------------------------------------------------------------------------
__global__ void sub_kernel(float* __restrict__ out) {
    long i = (long)blockIdx.x * blockDim.x + threadIdx.x;
    const long ng = (long)BATCH * (VOCAB / 8);
    if (i >= ng) return;
    int b = (int)(i / (VOCAB / 8));
    int j = (int)(i % (VOCAB / 8)) * 8;
    float l = g_lse[b];
    const uint4 pkt = *(const uint4*)(g_logit + (size_t)b * VSTR + j);
    const __nv_bfloat16* h = (const __nv_bfloat16*)&pkt;
    float4 o0, o1;
    o0.x = __bfloat162float(h[0]) - l; o0.y = __bfloat162float(h[1]) - l;
    o0.z = __bfloat162float(h[2]) - l; o0.w = __bfloat162float(h[3]) - l;
    o1.x = __bfloat162float(h[4]) - l; o1.y = __bfloat162float(h[5]) - l;
    o1.z = __bfloat162float(h[6]) - l; o1.w = __bfloat162float(h[7]) - l;
    float4* op = (float4*)(out + (size_t)b * VOCAB + j);
    op[0] = o0; op[1] = o1;
}

extern "C" void kernel_launch(void* const* d_in, const int* in_sizes, int n_in,
                              void* d_out, int out_size) {
    const int*   ctx = (const int*)d_in[0];
    const float* Wp  = (const float*)d_in[1];
    const float* Wc  = (const float*)d_in[2];
    const float* bc  = (const float*)d_in[3];
    const int*   pad = (const int*)d_in[4];
    float*       out = (float*)d_out;

    cudaFuncSetAttribute(gemm_kernel, cudaFuncAttributeMaxDynamicSharedMemorySize, SMEM_REQ);

    prep_kernel<<<BATCH + NCONV, 320>>>(ctx, Wp, pad, Wc, bc);   // idx 0
    gemm_kernel<<<dim3(NBT, NVT), 256, SMEM_REQ>>>();            // idx 1
    lse_kernel<<<BATCH, 256>>>();                                // idx 2
    sub_kernel<<<(int)(((long)BATCH * (VOCAB / 8) + 255) / 256), 256>>>(out);  // idx 3
}